// round 1
// baseline (speedup 1.0000x reference)
#include <cuda_runtime.h>
#include <cuda_bf16.h>
#include <math.h>

#define N_BINS 256

// Scratch: per-bin global accumulators (no cudaMalloc allowed).
__device__ float        g_binsum[N_BINS];
__device__ unsigned int g_bincnt[N_BINS];

// ---------------------------------------------------------------------------
// Kernel 0: zero the global accumulators (must run each replay; graph-safe).
// ---------------------------------------------------------------------------
__global__ void zero_kernel() {
    int t = threadIdx.x;            // blockDim.x == N_BINS
    g_binsum[t] = 0.0f;
    g_bincnt[t] = 0u;
}

// ---------------------------------------------------------------------------
// Kernel 1: single pass over y_pred / y_true.
//   idx = round(clip(y_true,-7,7)+7)/14 * 255)   (rintf == round-half-even,
//                                                 matching jnp.round)
//   accumulate per-bin count and per-bin sum of (pred-true)^2
// Privatized shared-memory histogram per block, flushed with global atomics.
// ---------------------------------------------------------------------------
__global__ void __launch_bounds__(256)
histo_sq_kernel(const float* __restrict__ y_pred,
                const float* __restrict__ y_true,
                long long n)            // total element count
{
    __shared__ float    s_sum[N_BINS];
    __shared__ unsigned s_cnt[N_BINS];

    const int t = threadIdx.x;
    s_sum[t] = 0.0f;
    s_cnt[t] = 0u;
    __syncthreads();

    const long long n4      = n >> 2;                  // float4 count
    const long long gthread = (long long)blockIdx.x * blockDim.x + t;
    const long long gstride = (long long)gridDim.x * blockDim.x;

    const float4* p4 = reinterpret_cast<const float4*>(y_pred);
    const float4* t4 = reinterpret_cast<const float4*>(y_true);

    const float kOff   = 7.0f;
    const float kScale = (1.0f / 14.0f);   // SCALE
    const float kBins  = 255.0f;           // N_BINS - 1

    for (long long i = gthread; i < n4; i += gstride) {
        float4 a = p4[i];
        float4 b = t4[i];

        {
            float d  = a.x - b.x;
            float c  = fminf(fmaxf(b.x, -kOff), kOff);
            int idx  = (int)rintf((c + kOff) * kScale * kBins);
            atomicAdd(&s_sum[idx], d * d);
            atomicAdd(&s_cnt[idx], 1u);
        }
        {
            float d  = a.y - b.y;
            float c  = fminf(fmaxf(b.y, -kOff), kOff);
            int idx  = (int)rintf((c + kOff) * kScale * kBins);
            atomicAdd(&s_sum[idx], d * d);
            atomicAdd(&s_cnt[idx], 1u);
        }
        {
            float d  = a.z - b.z;
            float c  = fminf(fmaxf(b.z, -kOff), kOff);
            int idx  = (int)rintf((c + kOff) * kScale * kBins);
            atomicAdd(&s_sum[idx], d * d);
            atomicAdd(&s_cnt[idx], 1u);
        }
        {
            float d  = a.w - b.w;
            float c  = fminf(fmaxf(b.w, -kOff), kOff);
            int idx  = (int)rintf((c + kOff) * kScale * kBins);
            atomicAdd(&s_sum[idx], d * d);
            atomicAdd(&s_cnt[idx], 1u);
        }
    }

    // Scalar tail (n not divisible by 4) — handled by block 0 only.
    if (blockIdx.x == 0) {
        for (long long i = (n4 << 2) + t; i < n; i += blockDim.x) {
            float d  = y_pred[i] - y_true[i];
            float c  = fminf(fmaxf(y_true[i], -kOff), kOff);
            int idx  = (int)rintf((c + kOff) * kScale * kBins);
            atomicAdd(&s_sum[idx], d * d);
            atomicAdd(&s_cnt[idx], 1u);
        }
    }

    __syncthreads();
    // One thread per bin flushes to global (blockDim == N_BINS).
    if (s_cnt[t] != 0u) {
        atomicAdd(&g_binsum[t], s_sum[t]);
        atomicAdd(&g_bincnt[t], s_cnt[t]);
    }
}

// ---------------------------------------------------------------------------
// Kernel 2: finalize. 256 threads; compute lut[b] and reduce
//   result = (1/n) * sum_b g_binsum[b] * 1/log1p(0.02 + cnt[b]/n)
// ---------------------------------------------------------------------------
__global__ void __launch_bounds__(256)
finalize_kernel(float* __restrict__ out, float inv_n)
{
    __shared__ float red[8];
    const int t    = threadIdx.x;
    const int lane = t & 31;
    const int wid  = t >> 5;

    float freq = (float)g_bincnt[t] * inv_n;
    float lut  = 1.0f / log1pf(0.02f + freq);
    float v    = g_binsum[t] * lut;

    // warp reduce
    #pragma unroll
    for (int o = 16; o > 0; o >>= 1)
        v += __shfl_down_sync(0xFFFFFFFFu, v, o);
    if (lane == 0) red[wid] = v;
    __syncthreads();
    if (wid == 0) {
        float s = (lane < 8) ? red[lane] : 0.0f;
        #pragma unroll
        for (int o = 4; o > 0; o >>= 1)
            s += __shfl_down_sync(0xFFFFFFFFu, s, o);
        if (lane == 0) out[0] = s * inv_n;
    }
}

// ---------------------------------------------------------------------------
extern "C" void kernel_launch(void* const* d_in, const int* in_sizes, int n_in,
                              void* d_out, int out_size)
{
    const float* y_pred = (const float*)d_in[0];
    const float* y_true = (const float*)d_in[1];
    float*       out    = (float*)d_out;

    const long long n = (long long)in_sizes[0];
    const float inv_n = 1.0f / (float)n;

    // 148 SMs * 8 resident blocks — grid-stride over float4 elements.
    const int blocks  = 148 * 8;
    const int threads = 256;

    zero_kernel<<<1, N_BINS>>>();
    histo_sq_kernel<<<blocks, threads>>>(y_pred, y_true, n);
    finalize_kernel<<<1, N_BINS>>>(out, inv_n);
}